// round 2
// baseline (speedup 1.0000x reference)
#include <cuda_runtime.h>
#include <cstdint>

#define B_   8
#define HW_  32
#define C_   32
#define F_   64
#define HO_  30
#define WO_  30
#define K_   288
#define KPAD 292   // pad so lane-stride banks are (4f+k)%32 -> LDS.128 conflict-free

// dynamic smem layout (floats):
//   w_sm : F_ * KPAD          = 18688   (w transposed: [f][k])
//   x_sm : 3 * 32 * 32        = 3072    (3 input rows for this ho)
//   b_sm : 64
#define SMEM_FLOATS (F_ * KPAD + 3 * HW_ * C_ + F_ + 32)
#define SMEM_BYTES  (SMEM_FLOATS * 4)

extern __shared__ float smem[];

// accumulate s = p + wk into running max/min (componentwise float4)
#define ACC4(mx, mn, p, wk)                                              \
    do {                                                                 \
        float s_;                                                        \
        s_ = (p).x + (wk).x; (mx).x = fmaxf((mx).x, s_); (mn).x = fminf((mn).x, s_); \
        s_ = (p).y + (wk).y; (mx).y = fmaxf((mx).y, s_); (mn).y = fminf((mn).y, s_); \
        s_ = (p).z + (wk).z; (mx).z = fmaxf((mx).z, s_); (mn).z = fminf((mn).z, s_); \
        s_ = (p).w + (wk).w; (mx).w = fmaxf((mx).w, s_); (mn).w = fminf((mn).w, s_); \
    } while (0)

__global__ __launch_bounds__(256, 2)
void tropconv_kernel(const float* __restrict__ x,
                     const float* __restrict__ w,
                     const float* __restrict__ bias,
                     float* __restrict__ out)
{
    float* w_sm = smem;                       // [F_][KPAD]
    float* x_sm = smem + F_ * KPAD;           // [3][32][32]
    float* b_sm = x_sm + 3 * HW_ * C_;        // [64]

    const int tid = threadIdx.y * 64 + threadIdx.x;
    const int row = blockIdx.x;               // = b*30 + ho
    const int ho  = row % HO_;
    const int b   = row / HO_;

    // ---- load w transposed into smem: w global is [k][f] (288 x 64) ----
    for (int idx = tid; idx < K_ * F_; idx += 256) {
        int k = idx >> 6;       // 0..287
        int f = idx & 63;       // 0..63
        w_sm[f * KPAD + k] = w[idx];
    }
    // ---- load 3-row x slab: rows ho..ho+2, full width, all channels ----
    const float* xbase = x + (b * HW_ + ho) * (HW_ * C_);
    for (int idx = tid; idx < 3 * HW_ * C_; idx += 256)
        x_sm[idx] = xbase[idx];
    if (tid < F_) b_sm[tid] = bias[tid];
    __syncthreads();

    const int f = threadIdx.x;                // filter 0..63
    const float4* wrowbase = (const float4*)(w_sm + f * KPAD);  // 16B aligned (292*4=1168)

    const float NINF = __int_as_float(0xff800000u);
    const float PINF = __int_as_float(0x7f800000u);

    // 4 passes x 4 ty-lanes x 2 wo each = wo pairs (0,1)..(28,29); (30,31) skipped
    for (int pass = 0; pass < 4; ++pass) {
        const int wo0 = pass * 8 + threadIdx.y * 2;
        if (wo0 >= WO_) break;                // only pass=3, ty=3
        const int wo1 = wo0 + 1;

        float4 mx0 = make_float4(NINF, NINF, NINF, NINF);
        float4 mn0 = make_float4(PINF, PINF, PINF, PINF);
        float4 mx1 = mx0;
        float4 mn1 = mn0;

        #pragma unroll
        for (int i = 0; i < 3; ++i) {
            #pragma unroll
            for (int j = 0; j < 3; ++j) {
                // patch vectors: channel axis contiguous -> direct vec4 from x slab
                const float4* p0 = (const float4*)(x_sm + (i * HW_ + wo0 + j) * C_);
                const float4* p1 = (const float4*)(x_sm + (i * HW_ + wo1 + j) * C_);
                const float4* wv = wrowbase + (i * 3 + j) * (C_ / 4);
                #pragma unroll
                for (int c4 = 0; c4 < C_ / 4; ++c4) {
                    float4 wk = wv[c4];       // conflict-free strided LDS.128
                    float4 a0 = p0[c4];       // uniform-address broadcast
                    float4 a1 = p1[c4];
                    ACC4(mx0, mn0, a0, wk);
                    ACC4(mx1, mn1, a1, wk);
                }
            }
        }

        // horizontal reduce + store (coalesced over f)
        float hx0 = fmaxf(fmaxf(mx0.x, mx0.y), fmaxf(mx0.z, mx0.w));
        float hn0 = fminf(fminf(mn0.x, mn0.y), fminf(mn0.z, mn0.w));
        float hx1 = fmaxf(fmaxf(mx1.x, mx1.y), fmaxf(mx1.z, mx1.w));
        float hn1 = fminf(fminf(mn1.x, mn1.y), fminf(mn1.z, mn1.w));
        float bv = b_sm[f];
        out[(row * WO_ + wo0) * F_ + f] = hx0 - hn0 + bv;
        out[(row * WO_ + wo1) * F_ + f] = hx1 - hn1 + bv;
    }
}

extern "C" void kernel_launch(void* const* d_in, const int* in_sizes, int n_in,
                              void* d_out, int out_size)
{
    const float* x    = (const float*)d_in[0];
    const float* w    = (const float*)d_in[1];
    const float* bias = (const float*)d_in[2];
    float* out        = (float*)d_out;

    cudaFuncSetAttribute(tropconv_kernel,
                         cudaFuncAttributeMaxDynamicSharedMemorySize, SMEM_BYTES);

    dim3 block(64, 4);
    tropconv_kernel<<<B_ * HO_, block, SMEM_BYTES>>>(x, w, bias, out);
}

// round 3
// speedup vs baseline: 1.0020x; 1.0020x over previous
#include <cuda_runtime.h>
#include <cstdint>

#define B_   8
#define HW_  32
#define C_   32
#define F_   64
#define HO_  30
#define WO_  30
#define K_   288
#define KPAD 292   // pad: lane stride (4f)%32 -> LDS.128 conflict-free; /4 for vec4 align

// dynamic smem (floats): w_sm [64][292] transposed, x_sm [3][32][32]
#define SMEM_FLOATS (F_ * KPAD + 3 * HW_ * C_)
#define SMEM_BYTES  (SMEM_FLOATS * 4)

extern __shared__ float smem[];

#define ACC4(mx, mn, p, wk)                                              \
    do {                                                                 \
        float s_;                                                        \
        s_ = (p).x + (wk).x; (mx).x = fmaxf((mx).x, s_); (mn).x = fminf((mn).x, s_); \
        s_ = (p).y + (wk).y; (mx).y = fmaxf((mx).y, s_); (mn).y = fminf((mn).y, s_); \
        s_ = (p).z + (wk).z; (mx).z = fmaxf((mx).z, s_); (mn).z = fminf((mn).z, s_); \
        s_ = (p).w + (wk).w; (mx).w = fmaxf((mx).w, s_); (mn).w = fminf((mn).w, s_); \
    } while (0)

__global__ __launch_bounds__(256, 2)
void tropconv_kernel(const float* __restrict__ x,
                     const float* __restrict__ w,
                     const float* __restrict__ bias,
                     float* __restrict__ out)
{
    float* w_sm = smem;                       // [F_][KPAD]
    float* x_sm = smem + F_ * KPAD;           // [3][32][32]

    const int tid = threadIdx.y * 64 + threadIdx.x;
    const int row = blockIdx.x;               // = b*30 + ho
    const int ho  = row % HO_;
    const int b   = row / HO_;

    // ---- w transposed into smem: global w is [k][f] (288 x 64) ----
    #pragma unroll 4
    for (int idx = tid; idx < K_ * F_; idx += 256) {
        int k = idx >> 6;
        int f = idx & 63;
        w_sm[f * KPAD + k] = w[idx];
    }
    // ---- 3-row x slab: rows ho..ho+2 ----
    const float* xbase = x + (b * HW_ + ho) * (HW_ * C_);
    #pragma unroll 4
    for (int idx = tid; idx < 3 * HW_ * C_; idx += 256)
        x_sm[idx] = xbase[idx];
    __syncthreads();

    const int f = threadIdx.x;                // filter 0..63 (lane = f % 32)
    const float4* wrow = (const float4*)(w_sm + f * KPAD);  // 292*4 = 1168B, 16B aligned
    const float bv = __ldg(bias + f);

    const float NINF = __int_as_float(0xff800000u);
    const float PINF = __int_as_float(0x7f800000u);

    // 2 passes x 4 ty x 4 wo = 32 wo slots (>=30; clamp cols, mask stores)
    #pragma unroll 1
    for (int pass = 0; pass < 2; ++pass) {
        const int wo_base = pass * 16 + threadIdx.y * 4;

        // 6 clamped column base pointers (cols wo_base .. wo_base+5)
        const float* pcol[6];
        #pragma unroll
        for (int u = 0; u < 6; ++u) {
            int col = wo_base + u;
            if (col > 31) col = 31;           // safe garbage; stores masked below
            pcol[u] = x_sm + col * C_;
        }

        float4 mx[4], mn[4];
        #pragma unroll
        for (int t = 0; t < 4; ++t) {
            mx[t] = make_float4(NINF, NINF, NINF, NINF);
            mn[t] = make_float4(PINF, PINF, PINF, PINF);
        }

        #pragma unroll 1
        for (int c4 = 0; c4 < C_ / 4; ++c4) {
            #pragma unroll
            for (int i = 0; i < 3; ++i) {
                // 6 patch vec4 (broadcast across warp: address independent of lane)
                float4 p[6];
                #pragma unroll
                for (int u = 0; u < 6; ++u)
                    p[u] = *(const float4*)(pcol[u] + i * (HW_ * C_) + c4 * 4);

                #pragma unroll
                for (int j = 0; j < 3; ++j) {
                    float4 wk = wrow[(i * 3 + j) * (C_ / 4) + c4];  // strided, conflict-free
                    #pragma unroll
                    for (int t = 0; t < 4; ++t)
                        ACC4(mx[t], mn[t], p[j + t], wk);
                }
            }
        }

        // horizontal reduce + coalesced store over f
        #pragma unroll
        for (int t = 0; t < 4; ++t) {
            int wo = wo_base + t;
            if (wo < WO_) {
                float hx = fmaxf(fmaxf(mx[t].x, mx[t].y), fmaxf(mx[t].z, mx[t].w));
                float hn = fminf(fminf(mn[t].x, mn[t].y), fminf(mn[t].z, mn[t].w));
                out[(row * WO_ + wo) * F_ + f] = hx - hn + bv;
            }
        }
    }
}

extern "C" void kernel_launch(void* const* d_in, const int* in_sizes, int n_in,
                              void* d_out, int out_size)
{
    const float* x    = (const float*)d_in[0];
    const float* w    = (const float*)d_in[1];
    const float* bias = (const float*)d_in[2];
    float* out        = (float*)d_out;

    cudaFuncSetAttribute(tropconv_kernel,
                         cudaFuncAttributeMaxDynamicSharedMemorySize, SMEM_BYTES);

    dim3 block(64, 4);
    tropconv_kernel<<<B_ * HO_, block, SMEM_BYTES>>>(x, w, bias, out);
}

// round 4
// speedup vs baseline: 1.1784x; 1.1760x over previous
#include <cuda_runtime.h>
#include <cstdint>

#define B_    8
#define HW_   32
#define C_    32
#define F_    64
#define FQ_   16      // filters per CTA (quarter)
#define HO_   30
#define WO_   30
#define K_    288
#define KPAD  292     // f-stride: per-8-lane-phase banks 4f..4f+28 disjoint -> LDS.128 conflict-free

// dynamic smem (floats): w_sm [16][292] transposed slice, x_sm [3][32][32]
#define SMEM_FLOATS (FQ_ * KPAD + 3 * HW_ * C_)
#define SMEM_BYTES  (SMEM_FLOATS * 4)

extern __shared__ float smem[];

#define ACC4(mx, mn, p, wk)                                              \
    do {                                                                 \
        float s_;                                                        \
        s_ = (p).x + (wk).x; (mx).x = fmaxf((mx).x, s_); (mn).x = fminf((mn).x, s_); \
        s_ = (p).y + (wk).y; (mx).y = fmaxf((mx).y, s_); (mn).y = fminf((mn).y, s_); \
        s_ = (p).z + (wk).z; (mx).z = fmaxf((mx).z, s_); (mn).z = fminf((mn).z, s_); \
        s_ = (p).w + (wk).w; (mx).w = fmaxf((mx).w, s_); (mn).w = fminf((mn).w, s_); \
    } while (0)

__global__ __launch_bounds__(128, 6)
void tropconv_kernel(const float* __restrict__ x,
                     const float* __restrict__ w,
                     const float* __restrict__ bias,
                     float* __restrict__ out)
{
    float* w_sm = smem;                       // [FQ_][KPAD]
    float* x_sm = smem + FQ_ * KPAD;          // [3][32][32]

    const int tid = threadIdx.x;              // 0..127
    const int fq  = blockIdx.x & 3;           // filter quarter 0..3
    const int row = blockIdx.x >> 2;          // b*30 + ho
    const int ho  = row % HO_;
    const int b   = row / HO_;

    // ---- w slice transposed into smem: global w is [k][64]; take cols fq*16..fq*16+15 ----
    // idx -> fl = idx%16, k = idx/16 ; global addr k*64 + fq*16 + fl (coalesced 64B x2 per warp)
    #pragma unroll 4
    for (int idx = tid; idx < K_ * FQ_; idx += 128) {
        int fl = idx & 15;
        int k  = idx >> 4;
        w_sm[fl * KPAD + k] = w[k * F_ + fq * FQ_ + fl];
    }
    // ---- 3-row x slab (vec4) ----
    const float4* xbase = (const float4*)(x + (b * HW_ + ho) * (HW_ * C_));
    float4* x_sm4 = (float4*)x_sm;
    #pragma unroll
    for (int idx = tid; idx < 3 * HW_ * C_ / 4; idx += 128)
        x_sm4[idx] = xbase[idx];
    __syncthreads();

    const int fl   = tid & 15;                // local filter 0..15
    const int slot = tid >> 4;                // wo-group 0..7
    const int wo_base = slot * 4;

    const float4* wrow = (const float4*)(w_sm + fl * KPAD);  // 1168B stride, 16B aligned
    const float bv = __ldg(bias + fq * FQ_ + fl);

    const float NINF = __int_as_float(0xff800000u);
    const float PINF = __int_as_float(0x7f800000u);

    // 6 clamped column base pointers (cols wo_base .. wo_base+5)
    const float* pcol[6];
    #pragma unroll
    for (int u = 0; u < 6; ++u) {
        int col = wo_base + u;
        if (col > 31) col = 31;               // safe garbage; stores masked below
        pcol[u] = x_sm + col * C_;
    }

    float4 mx[4], mn[4];
    #pragma unroll
    for (int t = 0; t < 4; ++t) {
        mx[t] = make_float4(NINF, NINF, NINF, NINF);
        mn[t] = make_float4(PINF, PINF, PINF, PINF);
    }

    #pragma unroll 1
    for (int c4 = 0; c4 < C_ / 4; ++c4) {
        #pragma unroll
        for (int i = 0; i < 3; ++i) {
            // 6 patch vec4 (2 distinct addrs per warp -> broadcast, conflict-free)
            float4 p[6];
            #pragma unroll
            for (int u = 0; u < 6; ++u)
                p[u] = *(const float4*)(pcol[u] + i * (HW_ * C_) + c4 * 4);

            #pragma unroll
            for (int j = 0; j < 3; ++j) {
                float4 wk = wrow[(i * 3 + j) * (C_ / 4) + c4];
                #pragma unroll
                for (int t = 0; t < 4; ++t)
                    ACC4(mx[t], mn[t], p[j + t], wk);
            }
        }
    }

    // horizontal reduce + store (16 consecutive f per half-warp -> 64B segments)
    #pragma unroll
    for (int t = 0; t < 4; ++t) {
        int wo = wo_base + t;
        if (wo < WO_) {
            float hx = fmaxf(fmaxf(mx[t].x, mx[t].y), fmaxf(mx[t].z, mx[t].w));
            float hn = fminf(fminf(mn[t].x, mn[t].y), fminf(mn[t].z, mn[t].w));
            out[(row * WO_ + wo) * F_ + fq * FQ_ + fl] = hx - hn + bv;
        }
    }
}

extern "C" void kernel_launch(void* const* d_in, const int* in_sizes, int n_in,
                              void* d_out, int out_size)
{
    const float* x    = (const float*)d_in[0];
    const float* w    = (const float*)d_in[1];
    const float* bias = (const float*)d_in[2];
    float* out        = (float*)d_out;

    cudaFuncSetAttribute(tropconv_kernel,
                         cudaFuncAttributeMaxDynamicSharedMemorySize, SMEM_BYTES);

    tropconv_kernel<<<B_ * HO_ * 4, 128, SMEM_BYTES>>>(x, w, bias, out);
}

// round 5
// speedup vs baseline: 2.0892x; 1.7728x over previous
#include <cuda_runtime.h>
#include <cuda_fp16.h>
#include <cstdint>

#define B_    8
#define HW_   32
#define C_    32
#define F_    64
#define FQ_   16
#define HO_   30
#define WO_   30
#define K_    288
#define KPADH 296   // halfs per w_sm row: stride 592B -> fl*148 mod 32 banks distinct per phase

// device scratch (allowed: __device__ globals, no allocation)
__device__ __align__(16) __half g_xh[B_ * HW_ * HW_ * C_];   // 262144 halfs
__device__ __align__(16) __half g_wT[F_ * K_];               // transposed w [f][k]

// ---- pre-pass: convert x to half, convert+transpose w to half ----
__global__ void convert_kernel(const float* __restrict__ x, const float* __restrict__ w)
{
    int b = blockIdx.x;
    if (b < 256) {
        // x: 65536 float4 -> half2 pairs
        int idx = b * 256 + threadIdx.x;
        float4 v = ((const float4*)x)[idx];
        __half2* dst = (__half2*)g_xh + idx * 2;
        dst[0] = __floats2half2_rn(v.x, v.y);
        dst[1] = __floats2half2_rn(v.z, v.w);
    } else {
        // wT[f*288 + k] = w[k*64 + f]
        int j = (b - 256) * 256 + threadIdx.x;
        if (j < F_ * K_) {
            int f = j / K_, k = j - f * K_;
            g_wT[j] = __float2half_rn(w[k * F_ + f]);
        }
    }
}

__device__ __forceinline__ __half2 f_as_h2(float f)
{
    __half2 h;
    unsigned u = __float_as_uint(f);
    memcpy(&h, &u, 4);
    return h;
}

#define ACCH(mx, mn, pf, wf)                                                    \
    do {                                                                        \
        __half2 s_;                                                             \
        s_ = __hadd2(f_as_h2(pf.x), f_as_h2(wf.x)); mx = __hmax2(mx, s_); mn = __hmin2(mn, s_); \
        s_ = __hadd2(f_as_h2(pf.y), f_as_h2(wf.y)); mx = __hmax2(mx, s_); mn = __hmin2(mn, s_); \
        s_ = __hadd2(f_as_h2(pf.z), f_as_h2(wf.z)); mx = __hmax2(mx, s_); mn = __hmin2(mn, s_); \
        s_ = __hadd2(f_as_h2(pf.w), f_as_h2(wf.w)); mx = __hmax2(mx, s_); mn = __hmin2(mn, s_); \
    } while (0)

__global__ __launch_bounds__(128, 7)
void tropconv_h2(const float* __restrict__ bias, float* __restrict__ out)
{
    __shared__ __align__(16) __half w_sm[FQ_ * KPADH];   // [16][296]
    __shared__ __align__(16) __half x_sm[3 * HW_ * C_];  // [3][32][32]

    const int tid = threadIdx.x;
    const int fq  = blockIdx.x & 3;
    const int row = blockIdx.x >> 2;          // b*30 + ho
    const int ho  = row % HO_;
    const int b   = row / HO_;

    // ---- w slice: 576 vec8 (16B) chunks, repacked to padded rows ----
    {
        const char* src = (const char*)(g_wT + fq * FQ_ * K_);
        char* dst = (char*)w_sm;
        #pragma unroll
        for (int idx = tid; idx < 576; idx += 128) {
            int fl = idx / 36;                // 36 chunks per 288-half row
            int k8 = idx - fl * 36;
            *(float4*)(dst + fl * (KPADH * 2) + k8 * 16) =
                *(const float4*)(src + fl * (K_ * 2) + k8 * 16);
        }
    }
    // ---- x slab: 3 rows = 384 vec8 chunks ----
    {
        const float4* src = (const float4*)(g_xh + (b * HW_ + ho) * (HW_ * C_));
        float4* dst = (float4*)x_sm;
        #pragma unroll
        for (int idx = tid; idx < 384; idx += 128)
            dst[idx] = src[idx];
    }
    __syncthreads();

    const int fl   = tid & 15;
    const int slot = tid >> 4;
    const int wo_base = slot * 4;

    const char* wrowb = (const char*)w_sm + fl * (KPADH * 2);   // 592B stride, 16B aligned
    const char* xb = (const char*)x_sm;
    const float bv = __ldg(bias + fq * FQ_ + fl);

    // clamped column byte-offsets (col*64B per (i=0) position)
    int coff[6];
    #pragma unroll
    for (int u = 0; u < 6; ++u) {
        int col = wo_base + u;
        if (col > 31) col = 31;
        coff[u] = col * 64;
    }

    const __half2 HNEG = __float2half2_rn(-65504.0f);
    const __half2 HPOS = __float2half2_rn(65504.0f);
    __half2 mx2[4], mn2[4];
    #pragma unroll
    for (int t = 0; t < 4; ++t) { mx2[t] = HNEG; mn2[t] = HPOS; }

    #pragma unroll 1
    for (int c4 = 0; c4 < 4; ++c4) {          // 4 chunks of 8 channels (4 half2)
        #pragma unroll
        for (int i = 0; i < 3; ++i) {
            float4 pv[6];                     // 6 columns x 4 half2 (broadcast loads)
            #pragma unroll
            for (int u = 0; u < 6; ++u)
                pv[u] = *(const float4*)(xb + i * 2048 + coff[u] + c4 * 16);

            #pragma unroll
            for (int j = 0; j < 3; ++j) {
                float4 wv = *(const float4*)(wrowb + (i * 3 + j) * 64 + c4 * 16);
                #pragma unroll
                for (int t = 0; t < 4; ++t)
                    ACCH(mx2[t], mn2[t], pv[j + t], wv);
            }
        }
    }

    #pragma unroll
    for (int t = 0; t < 4; ++t) {
        int wo = wo_base + t;
        if (wo < WO_) {
            float hx = fmaxf(__low2float(mx2[t]), __high2float(mx2[t]));
            float hn = fminf(__low2float(mn2[t]), __high2float(mn2[t]));
            out[(row * WO_ + wo) * F_ + fq * FQ_ + fl] = hx - hn + bv;
        }
    }
}

extern "C" void kernel_launch(void* const* d_in, const int* in_sizes, int n_in,
                              void* d_out, int out_size)
{
    const float* x    = (const float*)d_in[0];
    const float* w    = (const float*)d_in[1];
    const float* bias = (const float*)d_in[2];
    float* out        = (float*)d_out;

    // 256 blocks for x (65536 float4), 72 blocks for w (18432 elems)
    convert_kernel<<<256 + 72, 256>>>(x, w);
    tropconv_h2<<<B_ * HO_ * 4, 128>>>(bias, out);
}